// round 6
// baseline (speedup 1.0000x reference)
#include <cuda_runtime.h>

#define N 256
#define T 512
#define GRID 128         // 2 anchors per block
#define MAXE 512         // worst case: all labels identical

// Scratch (allocations forbidden)
__device__ float2   g_part[GRID];
__device__ unsigned g_count = 0;

__global__ void __launch_bounds__(T, 1)
fused_kernel(const int* __restrict__ raw,
             const float* __restrict__ emb,
             float* __restrict__ out) {
    __shared__ float  s_rd0[N], s_rd1[N];      // raw distances
    __shared__ float  s_dn0[N], s_dn1[N];      // masked distances
    __shared__ int    s_lab[N];
    __shared__ float2 s_wmax[8];
    __shared__ int    s_c0[8], s_c1[8];
    __shared__ float  s_ed[MAXE];              // compacted (sign = anchor)
    __shared__ float  s_val[MAXE];

    const int t    = threadIdx.x;
    const int lane = t & 31;
    const int w    = t >> 5;                   // 16 warps
    const int b    = blockIdx.x;
    const int i0   = 2 * b, i1 = 2 * b + 1;

    // --- Label decode (int64 vs int32 autodetect via block vote) ---
    int odd_nonzero = (t < 128) ? (raw[2 * t + 1] != 0) : 0;
    int is_int32 = __syncthreads_or(odd_nonzero);
    if (t < N) s_lab[t] = is_int32 ? raw[t] : raw[2 * t];

    // --- Anchor rows into per-lane registers (coalesced LDG.128) ---
    const float4* e4 = reinterpret_cast<const float4*>(emb);
    const float4 a0 = __ldg(e4 + i0 * 32 + lane);
    const float4 a1 = __ldg(e4 + i1 * 32 + lane);

    // --- Warp-cooperative distances: warp w owns rows 16w..16w+15 ---
    // d^2 = sum (a_i - a_k)^2  (== gram form to ~1e-6; d[i,i]=0 exactly in both)
    const int row0 = w * 16;
#pragma unroll
    for (int r = 0; r < 16; r++) {
        float4 x = __ldg(e4 + (row0 + r) * 32 + lane);   // coalesced 512B
        float e0x = x.x - a0.x, e0y = x.y - a0.y, e0z = x.z - a0.z, e0w = x.w - a0.w;
        float e1x = x.x - a1.x, e1y = x.y - a1.y, e1z = x.z - a1.z, e1w = x.w - a1.w;
        float s0 = e0x * e0x + e0y * e0y + e0z * e0z + e0w * e0w;
        float s1 = e1x * e1x + e1y * e1y + e1z * e1z + e1w * e1w;
#pragma unroll
        for (int off = 16; off > 0; off >>= 1) {          // fixed-order butterfly
            s0 += __shfl_xor_sync(0xffffffffu, s0, off);
            s1 += __shfl_xor_sync(0xffffffffu, s1, off);
        }
        if (lane == 0) {
            // clip(.,0) then clip(.,EPS) == max(.,EPS)
            s_rd0[row0 + r] = sqrtf(fmaxf(s0, 1e-4f));
            s_rd1[row0 + r] = sqrtf(fmaxf(s1, 1e-4f));
        }
    }
    __syncthreads();                                      // bar A: rd + labels ready

    // --- Mask, per-warp max, ballots (threads 0..255 = warps 0..7) ---
    float d0 = 0.f, d1 = 0.f;
    bool pos0 = false, pos1 = false;
    unsigned b0 = 0, b1 = 0;
    if (t < N) {
        const int k = t;
        d0 = s_rd0[k];
        d1 = s_rd1[k];
        const int lk = s_lab[k], l0 = s_lab[i0], l1 = s_lab[i1];
        const bool neg0 = (lk != l0) || (k == i0);
        const bool neg1 = (lk != l1) || (k == i1);
        pos0 = (lk == l0) && (k != i0);
        pos1 = (lk == l1) && (k != i1);

        // masked distances (d >= 0.01 > -1, -1 never passes "> d")
        const float dn0 = neg0 ? d0 : -1.f;
        const float dn1 = neg1 ? d1 : -1.f;
        s_dn0[k] = dn0;
        s_dn1[k] = dn1;

        float a = dn0, c = dn1;
#pragma unroll
        for (int off = 16; off > 0; off >>= 1) {
            a = fmaxf(a, __shfl_xor_sync(0xffffffffu, a, off));
            c = fmaxf(c, __shfl_xor_sync(0xffffffffu, c, off));
        }
        b0 = __ballot_sync(0xffffffffu, pos0);
        b1 = __ballot_sync(0xffffffffu, pos1);
        if (lane == 0) {
            s_wmax[w] = make_float2(a, c);
            s_c0[w] = __popc(b0);
            s_c1[w] = __popc(b1);
        }
    }
    __syncthreads();                                      // bar B

    // --- Deterministic compaction slots + block maxd + counts (all threads) ---
    int C0 = 0, C1 = 0, p0 = 0, p1 = 0;
    float max0 = -1.f, max1 = -1.f;
#pragma unroll
    for (int q = 0; q < 8; q++) {
        int c0 = s_c0[q], c1 = s_c1[q];
        if (q < w) { p0 += c0; p1 += c1; }
        C0 += c0; C1 += c1;
        float2 wm = s_wmax[q];
        max0 = fmaxf(max0, wm.x);
        max1 = fmaxf(max1, wm.y);
    }
    const int C = C0 + C1;

    if (t < N) {
        unsigned lt = (1u << lane) - 1u;
        // anchor0 entries in [0, C0): +d0; anchor1 in [C0, C): -d1
        if (pos0) s_ed[p0 + __popc(b0 & lt)] = d0;
        if (pos1) s_ed[C0 + p1 + __popc(b1 & lt)] = -d1;
    }
    __syncthreads();                                      // bar C

    // --- Warp-cooperative successor-min scan, one entry per warp round ---
    for (int e = w; e < C; e += 16) {
        float dve = s_ed[e];                              // broadcast
        const bool  a1f = (dve < 0.f);
        const float dv  = fabsf(dve);
        const float4* p = a1f ? (const float4*)s_dn1 : (const float4*)s_dn0;
        float4 u = p[lane], v = p[lane + 32];             // conflict-free LDS.128
        float m = 3.402823466e+38f;
        if (u.x > dv) m = fminf(m, u.x);
        if (u.y > dv) m = fminf(m, u.y);
        if (u.z > dv) m = fminf(m, u.z);
        if (u.w > dv) m = fminf(m, u.w);
        if (v.x > dv) m = fminf(m, v.x);
        if (v.y > dv) m = fminf(m, v.y);
        if (v.z > dv) m = fminf(m, v.z);
        if (v.w > dv) m = fminf(m, v.w);
#pragma unroll
        for (int off = 16; off > 0; off >>= 1)
            m = fminf(m, __shfl_xor_sync(0xffffffffu, m, off));
        if (lane == 0) {
            const float mx = a1f ? max1 : max0;
            // mask_final <=> exists d_ij > d_ik <=> maxd > d_ik
            const float semi = (mx > dv) ? (dv - m) : (dv - mx);
            s_val[e] = fmaxf(0.f, semi + 1.0f);
        }
    }
    __syncthreads();                                      // bar D

    // --- Warp 0: fixed-order block sum + cross-block handoff ---
    if (t < 32) {
        float sv = 0.f;
        for (int e = lane; e < C; e += 32) sv += s_val[e];
#pragma unroll
        for (int off = 16; off > 0; off >>= 1)
            sv += __shfl_xor_sync(0xffffffffu, sv, off);

        unsigned rank = 0;
        if (lane == 0) {
            g_part[b] = make_float2(sv, (float)C);
            __threadfence();
            rank = atomicAdd(&g_count, 1u);
        }
        rank = __shfl_sync(0xffffffffu, rank, 0);

        // --- Last block: deterministic final reduction over 128 partials ---
        if (rank == GRID - 1) {
            float sx = 0.f, sy = 0.f;
#pragma unroll
            for (int q = 0; q < 4; q++) {
                const float2* gp = (const float2*)g_part + lane + q * 32;
                float2 vv;
                asm volatile("ld.global.cg.v2.f32 {%0,%1}, [%2];"
                             : "=f"(vv.x), "=f"(vv.y) : "l"(gp));
                sx += vv.x; sy += vv.y;
            }
#pragma unroll
            for (int off = 16; off > 0; off >>= 1) {
                sx += __shfl_xor_sync(0xffffffffu, sx, off);
                sy += __shfl_xor_sync(0xffffffffu, sy, off);
            }
            if (lane == 0) {
                out[0] = sx / sy;
                g_count = 0;                              // reset for replay
            }
        }
    }
}

extern "C" void kernel_launch(void* const* d_in, const int* in_sizes, int n_in,
                              void* d_out, int out_size) {
    const float* emb = (const float*)d_in[0];
    const int*   lab = (const int*)d_in[1];  // int32 view; kernel autodetects int64
    (void)in_sizes; (void)n_in; (void)out_size;

    fused_kernel<<<GRID, T>>>(lab, emb, (float*)d_out);
}

// round 7
// speedup vs baseline: 1.3423x; 1.3423x over previous
#include <cuda_runtime.h>

#define N 256
#define T 512
#define GRID 128         // 2 anchors per block
#define MAXE 512
#define PROW 257         // padded partials row stride (float2 units)

// Scratch (allocations forbidden)
__device__ float2   g_part[GRID];
__device__ unsigned g_count = 0;

// Dynamic smem: p[32][257] float2 | lab[256] | dn0[256] | dn1[256]
//               | wmax[8] f2 | c0[8] | c1[8] | ed[512] | val[512]
#define SMEM_BYTES (32 * PROW * 8 + N * 4 + 2 * N * 4 + 8 * 8 + 16 * 4 + 2 * MAXE * 4)

extern __shared__ char smem_raw[];

__global__ void __launch_bounds__(T, 1)
fused_kernel(const int* __restrict__ raw,
             const float* __restrict__ emb,
             float* __restrict__ out) {
    float2* s_p    = (float2*)smem_raw;                 // [32][PROW]
    int*    s_lab  = (int*)(smem_raw + 32 * PROW * 8);
    float*  s_dn0  = (float*)(s_lab + N);
    float*  s_dn1  = s_dn0 + N;
    float2* s_wmax = (float2*)(s_dn1 + N);
    int*    s_c0   = (int*)(s_wmax + 8);
    int*    s_c1   = s_c0 + 8;
    float*  s_ed   = (float*)(s_c1 + 8);
    float*  s_val  = s_ed + MAXE;

    const int t    = threadIdx.x;
    const int lane = t & 31;
    const int w    = t >> 5;                   // 16 warps
    const int b    = blockIdx.x;
    const int i0   = 2 * b, i1 = 2 * b + 1;

    // --- Label decode (int64 vs int32 autodetect via block vote) ---
    int odd_nonzero = (t < 128) ? (raw[2 * t + 1] != 0) : 0;
    int is_int32 = __syncthreads_or(odd_nonzero);
    if (t < N) s_lab[t] = is_int32 ? raw[t] : raw[2 * t];

    // --- Anchor rows: lane = column chunk (coalesced LDG.128) ---
    const float4* e4 = reinterpret_cast<const float4*>(emb);
    const float4 a0 = __ldg(e4 + i0 * 32 + lane);
    const float4 a1 = __ldg(e4 + i1 * 32 + lane);

    // --- Per-lane partial squared distances; warp w, iter j -> row w+16j ---
    // d^2 = sum (a_i - a_k)^2 ; partial over this lane's 4 columns
#pragma unroll
    for (int j = 0; j < 16; j++) {
        const int row = w + 16 * j;
        float4 x = __ldg(e4 + row * 32 + lane);          // coalesced 512B
        float e0 = x.x - a0.x; float s0 = e0 * e0;
        float f0 = x.x - a1.x; float s1 = f0 * f0;
        e0 = x.y - a0.y; s0 += e0 * e0;
        f0 = x.y - a1.y; s1 += f0 * f0;
        e0 = x.z - a0.z; s0 += e0 * e0;
        f0 = x.z - a1.z; s1 += f0 * f0;
        e0 = x.w - a0.w; s0 += e0 * e0;
        f0 = x.w - a1.w; s1 += f0 * f0;
        s_p[lane * PROW + row] = make_float2(s0, s1);    // conflict-free STS.64
    }
    __syncthreads();                                     // bar A: partials + labels

    // --- Threads 0..255: transpose-reduce 32 partials for row k ---
    float d0 = 0.f, d1 = 0.f;
    bool pos0 = false, pos1 = false;
    unsigned b0 = 0, b1 = 0;
    if (t < N) {
        const int k = t;
        float ax = 0.f, ay = 0.f, bx = 0.f, by = 0.f, cx = 0.f, cy = 0.f, dx = 0.f, dy = 0.f;
#pragma unroll
        for (int l = 0; l < 32; l += 4) {                // conflict-free LDS.64
            float2 v0 = s_p[(l + 0) * PROW + k];
            float2 v1 = s_p[(l + 1) * PROW + k];
            float2 v2 = s_p[(l + 2) * PROW + k];
            float2 v3 = s_p[(l + 3) * PROW + k];
            ax += v0.x; ay += v0.y;
            bx += v1.x; by += v1.y;
            cx += v2.x; cy += v2.y;
            dx += v3.x; dy += v3.y;
        }
        const float s0 = (ax + bx) + (cx + dx);          // fixed combine order
        const float s1 = (ay + by) + (cy + dy);
        // clip(.,0) then clip(.,EPS) == max(.,EPS)
        d0 = sqrtf(fmaxf(s0, 1e-4f));
        d1 = sqrtf(fmaxf(s1, 1e-4f));

        const int lk = s_lab[k], l0 = s_lab[i0], l1 = s_lab[i1];
        const bool neg0 = (lk != l0) || (k == i0);
        const bool neg1 = (lk != l1) || (k == i1);
        pos0 = (lk == l0) && (k != i0);
        pos1 = (lk == l1) && (k != i1);

        // masked distances (d >= 0.01 > -1, -1 never passes "> d")
        const float dn0 = neg0 ? d0 : -1.f;
        const float dn1 = neg1 ? d1 : -1.f;
        s_dn0[k] = dn0;
        s_dn1[k] = dn1;

        float a = dn0, c = dn1;
#pragma unroll
        for (int off = 16; off > 0; off >>= 1) {         // fixed-order butterfly (cheap, once)
            a = fmaxf(a, __shfl_xor_sync(0xffffffffu, a, off));
            c = fmaxf(c, __shfl_xor_sync(0xffffffffu, c, off));
        }
        b0 = __ballot_sync(0xffffffffu, pos0);
        b1 = __ballot_sync(0xffffffffu, pos1);
        if (lane == 0) {
            s_wmax[w] = make_float2(a, c);
            s_c0[w] = __popc(b0);
            s_c1[w] = __popc(b1);
        }
    }
    __syncthreads();                                     // bar B

    // --- Deterministic compaction slots + block maxd + counts ---
    int C0 = 0, C1 = 0, p0 = 0, p1 = 0;
    float max0 = -1.f, max1 = -1.f;
#pragma unroll
    for (int q = 0; q < 8; q++) {
        int c0 = s_c0[q], c1 = s_c1[q];
        if (q < w) { p0 += c0; p1 += c1; }
        C0 += c0; C1 += c1;
        float2 wm = s_wmax[q];
        max0 = fmaxf(max0, wm.x);
        max1 = fmaxf(max1, wm.y);
    }
    const int C = C0 + C1;

    if (t < N) {
        unsigned lt = (1u << lane) - 1u;
        // anchor0 entries in [0, C0): +d0; anchor1 in [C0, C): -d1
        if (pos0) s_ed[p0 + __popc(b0 & lt)] = d0;
        if (pos1) s_ed[C0 + p1 + __popc(b1 & lt)] = -d1;
    }
    __syncthreads();                                     // bar C

    // --- Warp-cooperative successor-min scan, one entry per warp round ---
    for (int e = w; e < C; e += 16) {
        float dve = s_ed[e];                             // broadcast
        const bool  a1f = (dve < 0.f);
        const float dv  = fabsf(dve);
        const float4* p = a1f ? (const float4*)s_dn1 : (const float4*)s_dn0;
        float4 u = p[lane], v = p[lane + 32];            // conflict-free LDS.128
        float m = 3.402823466e+38f;
        if (u.x > dv) m = fminf(m, u.x);
        if (u.y > dv) m = fminf(m, u.y);
        if (u.z > dv) m = fminf(m, u.z);
        if (u.w > dv) m = fminf(m, u.w);
        if (v.x > dv) m = fminf(m, v.x);
        if (v.y > dv) m = fminf(m, v.y);
        if (v.z > dv) m = fminf(m, v.z);
        if (v.w > dv) m = fminf(m, v.w);
#pragma unroll
        for (int off = 16; off > 0; off >>= 1)
            m = fminf(m, __shfl_xor_sync(0xffffffffu, m, off));
        if (lane == 0) {
            const float mx = a1f ? max1 : max0;
            // mask_final <=> exists d_ij > d_ik <=> maxd > d_ik
            const float semi = (mx > dv) ? (dv - m) : (dv - mx);
            s_val[e] = fmaxf(0.f, semi + 1.0f);
        }
    }
    __syncthreads();                                     // bar D

    // --- Warp 0: fixed-order block sum + cross-block handoff ---
    if (t < 32) {
        float sv = 0.f;
        for (int e = lane; e < C; e += 32) sv += s_val[e];
#pragma unroll
        for (int off = 16; off > 0; off >>= 1)
            sv += __shfl_xor_sync(0xffffffffu, sv, off);

        unsigned rank = 0;
        if (lane == 0) {
            g_part[b] = make_float2(sv, (float)C);
            __threadfence();
            rank = atomicAdd(&g_count, 1u);
        }
        rank = __shfl_sync(0xffffffffu, rank, 0);

        // --- Last block: deterministic final reduction over 128 partials ---
        if (rank == GRID - 1) {
            float sx = 0.f, sy = 0.f;
#pragma unroll
            for (int q = 0; q < 4; q++) {
                const float2* gp = (const float2*)g_part + lane + q * 32;
                float2 vv;
                asm volatile("ld.global.cg.v2.f32 {%0,%1}, [%2];"
                             : "=f"(vv.x), "=f"(vv.y) : "l"(gp));
                sx += vv.x; sy += vv.y;
            }
#pragma unroll
            for (int off = 16; off > 0; off >>= 1) {
                sx += __shfl_xor_sync(0xffffffffu, sx, off);
                sy += __shfl_xor_sync(0xffffffffu, sy, off);
            }
            if (lane == 0) {
                out[0] = sx / sy;
                g_count = 0;                             // reset for replay
            }
        }
    }
}

extern "C" void kernel_launch(void* const* d_in, const int* in_sizes, int n_in,
                              void* d_out, int out_size) {
    const float* emb = (const float*)d_in[0];
    const int*   lab = (const int*)d_in[1];  // int32 view; kernel autodetects int64
    (void)in_sizes; (void)n_in; (void)out_size;

    cudaFuncSetAttribute(fused_kernel,
                         cudaFuncAttributeMaxDynamicSharedMemorySize, SMEM_BYTES);
    fused_kernel<<<GRID, T, SMEM_BYTES>>>(lab, emb, (float*)d_out);
}